// round 8
// baseline (speedup 1.0000x reference)
#include <cuda_runtime.h>
#include <cstdint>

#define NQ 2048
#define NT 5
#define NB 32
#define NCH 4                 // chunks per target
#define NW (NT * NCH)         // 20 warps
#define TPB (NW * 32)         // 640 threads
#define QCHUNK (NQ / NCH)     // 512 queries per warp
#define NCAND 3125            // 5^5

static __device__ __forceinline__ unsigned long long umin64(unsigned long long a,
                                                            unsigned long long b) {
    return a < b ? a : b;
}
static __device__ __forceinline__ unsigned long long umax64(unsigned long long a,
                                                            unsigned long long b) {
    return a > b ? a : b;
}
#define CE(a, b) { unsigned long long _lo = umin64(a, b); b = umax64(a, b); a = _lo; }

// Merge sorted-ascending a[5] with DESCENDING b[5]; keep 5 smallest sorted in a.
static __device__ __forceinline__ void merge_top5_rev(unsigned long long* a,
                                                      const unsigned long long* brev) {
    unsigned long long s0 = umin64(a[0], brev[0]);
    unsigned long long s1 = umin64(a[1], brev[1]);
    unsigned long long s2 = umin64(a[2], brev[2]);
    unsigned long long s3 = umin64(a[3], brev[3]);
    unsigned long long s4 = umin64(a[4], brev[4]);
    CE(s0, s1); CE(s3, s4); CE(s2, s4); CE(s2, s3); CE(s0, s3);
    CE(s0, s2); CE(s1, s4); CE(s1, s3); CE(s1, s2);
    a[0] = s0; a[1] = s1; a[2] = s2; a[3] = s3; a[4] = s4;
}

__global__ __launch_bounds__(TPB, 1)
void hungarian_match_kernel(const float* __restrict__ pred_regs,   // [32,2048,3]
                            const float* __restrict__ tgt,         // [160,3]
                            float* __restrict__ out)               // [2,32,5] f32
{
    __shared__ unsigned long long sm_lists[NW][NT];
    __shared__ int   sel_idx[NT][NT];
    __shared__ float sel_val[NT][NT];
    __shared__ unsigned long long red[NW];

    const int b    = blockIdx.x;
    const int tid  = threadIdx.x;
    const int w    = tid >> 5;
    const int lane = tid & 31;
    const int t    = w >> 2;      // target 0..4
    const int ch   = w & 3;       // chunk 0..3

    // ---- target coords for this warp (broadcast) ----
    const float t0f = __ldg(&tgt[b * NT * 3 + t * 3 + 0]);
    const float t1f = __ldg(&tgt[b * NT * 3 + t * 3 + 1]);
    const float t2f = __ldg(&tgt[b * NT * 3 + t * 3 + 2]);

    // ---- per-lane top-5 over 16 queries, float4 loads (3 LDG.128 / 4 q) ----
    // key = float_bits(cost)<<32 | q ; costs >= 1 > 0 so uint order == float
    // order; unique keys make processing order irrelevant while reproducing
    // jax.lax.top_k's stable tie-break exactly.
    const float* pr = pred_regs + (size_t)b * NQ * 3;
    unsigned long long m[NT] = {~0ULL, ~0ULL, ~0ULL, ~0ULL, ~0ULL};

    #pragma unroll
    for (int i = 0; i < 4; i++) {
        const int q0 = ch * QCHUNK + i * 128 + lane * 4;   // q0 % 4 == 0
        const float4* p4 = (const float4*)(pr + (size_t)q0 * 3);
        float4 va = __ldg(&p4[0]);
        float4 vb = __ldg(&p4[1]);
        float4 vc = __ldg(&p4[2]);

        float px[4], py[4], pz[4];
        px[0] = va.x; py[0] = va.y; pz[0] = va.z;
        px[1] = va.w; py[1] = vb.x; pz[1] = vb.y;
        px[2] = vb.z; py[2] = vb.w; pz[2] = vc.x;
        px[3] = vc.y; py[3] = vc.z; pz[3] = vc.w;

        #pragma unroll
        for (int j = 0; j < 4; j++) {
            float a0 = fabsf(__fsub_rn(px[j], t0f));
            float a1 = fabsf(__fsub_rn(py[j], t1f));
            float a2 = fabsf(__fsub_rn(pz[j], t2f));
            float c  = __fadd_rn(__fadd_rn(__fadd_rn(a0, a1), a2), 1.0f);
            unsigned long long key =
                ((unsigned long long)__float_as_uint(c) << 32) |
                (unsigned int)(q0 + j);
            if (key < m[4]) {
                m[4] = key;
                unsigned long long tmp;
                if (m[4] < m[3]) { tmp = m[3]; m[3] = m[4]; m[4] = tmp; }
                if (m[3] < m[2]) { tmp = m[2]; m[2] = m[3]; m[3] = tmp; }
                if (m[2] < m[1]) { tmp = m[1]; m[1] = m[2]; m[2] = tmp; }
                if (m[1] < m[0]) { tmp = m[0]; m[0] = m[1]; m[1] = tmp; }
            }
        }
    }

    // ---- warp bitonic merge: 5 levels; every lane ends with warp top-5 ----
    #pragma unroll
    for (int off = 16; off > 0; off >>= 1) {
        unsigned long long o[NT];
        #pragma unroll
        for (int k = 0; k < NT; k++)
            o[NT - 1 - k] = __shfl_xor_sync(0xffffffffu, m[k], off);
        merge_top5_rev(m, o);
    }
    if (lane == 0) {
        #pragma unroll
        for (int k = 0; k < NT; k++) sm_lists[w][k] = m[k];
    }
    __syncthreads();

    // ---- threads 0..4: register-resident 4-way merge for target tid ----
    if (tid < NT) {
        unsigned long long A[NT], B[NT];
        #pragma unroll
        for (int k = 0; k < NT; k++) A[k] = sm_lists[tid * NCH + 0][k];
        #pragma unroll
        for (int j = 1; j < NCH; j++) {
            #pragma unroll
            for (int k = 0; k < NT; k++) B[k] = sm_lists[tid * NCH + j][NT - 1 - k];
            merge_top5_rev(A, B);
        }
        #pragma unroll
        for (int k = 0; k < NT; k++) {
            sel_idx[tid][k] = (int)(unsigned int)A[k];
            sel_val[tid][k] = __uint_as_float((unsigned int)(A[k] >> 32));
        }
    }
    __syncthreads();

    // ---- 3125 tuples over 640 threads; argmin of f32 sum, first-occurrence ----
    unsigned long long best = ~0ULL;
    #pragma unroll
    for (int it = 0; it < 5; it++) {
        int n = tid + it * TPB;
        if (n < NCAND) {
            int r  = n;
            int d0 = r / 625;  r -= d0 * 625;
            int d1 = r / 125;  r -= d1 * 125;
            int d2 = r / 25;   r -= d2 * 25;
            int d3 = r / 5;
            int d4 = r - d3 * 5;
            int q0 = sel_idx[0][d0], q1 = sel_idx[1][d1], q2 = sel_idx[2][d2],
                q3 = sel_idx[3][d3], q4 = sel_idx[4][d4];
            bool valid = (q0 != q1) && (q0 != q2) && (q0 != q3) && (q0 != q4) &&
                         (q1 != q2) && (q1 != q3) && (q1 != q4) &&
                         (q2 != q3) && (q2 != q4) && (q3 != q4);
            if (valid) {
                float tot = __fadd_rn(
                                __fadd_rn(
                                    __fadd_rn(
                                        __fadd_rn(sel_val[0][d0], sel_val[1][d1]),
                                        sel_val[2][d2]),
                                    sel_val[3][d3]),
                                sel_val[4][d4]);
                unsigned long long key =
                    ((unsigned long long)__float_as_uint(tot) << 32) |
                    (unsigned int)n;
                best = umin64(best, key);
            }
        }
    }
    #pragma unroll
    for (int s = 16; s > 0; s >>= 1)
        best = umin64(best, __shfl_xor_sync(0xffffffffu, best, s));
    if (lane == 0) red[w] = best;
    __syncthreads();

    // ---- warp 0: parallel final reduce; lane 0 decodes + writes ----
    if (w == 0) {
        unsigned long long bb = (lane < NW) ? red[lane] : ~0ULL;
        #pragma unroll
        for (int s = 16; s > 0; s >>= 1)
            bb = umin64(bb, __shfl_xor_sync(0xffffffffu, bb, s));
        if (lane == 0) {
            int n = (int)(unsigned int)bb;
            int d[NT];
            d[0] = n / 625; n %= 625;
            d[1] = n / 125; n %= 125;
            d[2] = n / 25;  n %= 25;
            d[3] = n / 5;
            d[4] = n % 5;
            int rows[NT], cols[NT];
            #pragma unroll
            for (int j = 0; j < NT; j++) { rows[j] = sel_idx[j][d[j]]; cols[j] = j; }
            #pragma unroll
            for (int i = 1; i < NT; i++) {     // stable insertion sort by rows
                int rv = rows[i], cv = cols[i], j = i - 1;
                while (j >= 0 && rows[j] > rv) {
                    rows[j + 1] = rows[j]; cols[j + 1] = cols[j]; j--;
                }
                rows[j + 1] = rv; cols[j + 1] = cv;
            }
            #pragma unroll
            for (int j = 0; j < NT; j++) {
                out[b * NT + j]           = (float)rows[j];   // rows [32,5]
                out[NB * NT + b * NT + j] = (float)cols[j];   // cols [32,5]
            }
        }
    }
}

extern "C" void kernel_launch(void* const* d_in, const int* in_sizes, int n_in,
                              void* d_out, int out_size) {
    // Bind by size (confirmed working): pred_regs = 196608 f32, tgt = 480 f32.
    int pr_i = -1, tg_i = -1, max_i = 0;
    for (int i = 0; i < n_in; i++) {
        if (in_sizes[i] == 196608 || in_sizes[i] == 786432) pr_i = i;
        if (in_sizes[i] == 480    || in_sizes[i] == 1920)   tg_i = i;
        if (in_sizes[i] > in_sizes[max_i]) max_i = i;
    }
    if (pr_i < 0) pr_i = max_i;
    if (tg_i < 0) tg_i = (n_in > 3) ? 3 : n_in - 1;

    const float* pred_regs = (const float*)d_in[pr_i];
    const float* tgt       = (const float*)d_in[tg_i];
    float* out = (float*)d_out;
    hungarian_match_kernel<<<NB, TPB>>>(pred_regs, tgt, out);
}